// round 10
// baseline (speedup 1.0000x reference)
#include <cuda_runtime.h>
#include <stdint.h>

// out[b,q,k] (f32 0/1) = (kmin <= k <= kmax) & (expl[q,k]!=0) & (qseg[b,q]==kseg[b,k])
//   kmax = q + min(off,0), kmin = q - win + 1
//
// Persistent grid-stride over output rows (batch-inner order -> explicit row is
// read from DRAM once per q and reused across B via L2). Per row the band chunk
// range [lo,hi) is precomputed; outside it, branchless zero-store streams.

__global__ void __launch_bounds__(512)
mask_row_kernel(const int* __restrict__ expl,   // [qlen, klen]
                const int* __restrict__ qseg,   // [B, qlen]
                const int* __restrict__ kseg,   // [B, klen]
                float*     __restrict__ out,    // [B, qlen, klen]
                int qlen, int klen, int B, int nrows,
                int off_imm, int win_imm,
                const int* off_dev, const int* win_dev)
{
    const int off = off_dev ? __ldg(off_dev) : off_imm;
    const int win = win_dev ? __ldg(win_dev) : win_imm;

    const int n4  = klen >> 2;
    const int tid = threadIdx.x;
    const int bs  = blockDim.x;
    const float4 zero = make_float4(0.f, 0.f, 0.f, 0.f);

    for (int rowid = blockIdx.x; rowid < nrows; rowid += gridDim.x) {
        const int b = rowid % B;           // batch-inner
        const int q = rowid / B;

        const int kmax = q + (off < 0 ? off : 0);
        const int kmin = q - win + 1;

        float4*     orow = reinterpret_cast<float4*>(out + ((long long)b * qlen + q) * klen);
        const int4* erow = reinterpret_cast<const int4*>(expl + (long long)q * klen);
        const int4* krow = reinterpret_cast<const int4*>(kseg + (long long)b * klen);

        int lo = kmin >> 2;           if (lo < 0)  lo = 0;
        int hi = (kmax >> 2) + 1;     if (hi > n4) hi = n4;
        if (hi < lo) hi = lo;         if (lo > n4) lo = n4;

        // leading zeros
        #pragma unroll 4
        for (int i = tid; i < lo; i += bs)
            orow[i] = zero;

        // band
        const int qs = __ldg(qseg + b * qlen + q);
        for (int i = lo + tid; i < hi; i += bs) {
            const int k0 = i << 2;
            const int4 e  = __ldg(erow + i);
            const int4 ks = __ldg(krow + i);
            float4 r;
            r.x = ((k0   >= kmin) & (k0   <= kmax) & (e.x != 0) & (qs == ks.x)) ? 1.f : 0.f;
            r.y = ((k0+1 >= kmin) & (k0+1 <= kmax) & (e.y != 0) & (qs == ks.y)) ? 1.f : 0.f;
            r.z = ((k0+2 >= kmin) & (k0+2 <= kmax) & (e.z != 0) & (qs == ks.z)) ? 1.f : 0.f;
            r.w = ((k0+3 >= kmin) & (k0+3 <= kmax) & (e.w != 0) & (qs == ks.w)) ? 1.f : 0.f;
            orow[i] = r;
        }

        // trailing zeros
        #pragma unroll 4
        for (int i = hi + tid; i < n4; i += bs)
            orow[i] = zero;
    }
}

// Elementwise fallback (klen % 4 != 0; not expected for 8192).
__global__ void __launch_bounds__(256)
mask1_kernel(const int* __restrict__ expl,
             const int* __restrict__ qseg,
             const int* __restrict__ kseg,
             float*     __restrict__ out,
             int qlen, int klen, int off, int win,
             const int* off_dev, const int* win_dev,
             long long total)
{
    long long idx = (long long)blockIdx.x * blockDim.x + threadIdx.x;
    if (idx >= total) return;
    if (off_dev) off = __ldg(off_dev);
    if (win_dev) win = __ldg(win_dev);
    const int k = (int)(idx % klen);
    const long long row = idx / klen;
    const int q = (int)(row % qlen);
    const int b = (int)(row / qlen);
    const int d = q - k;
    const bool ok = (d >= -off) & (d >= 0) & (d < win)
                  & (expl[(long long)q * klen + k] != 0)
                  & (qseg[row] == kseg[(long long)b * klen + k]);
    out[idx] = ok ? 1.f : 0.f;
}

// Decode a size-1 scalar input. mode: 0 = immediate value, 1 = device pointer.
static int read_scalar(const void* p, int* mode, const int** dev_ptr)
{
    *mode = 0; *dev_ptr = nullptr;
    const uint64_t v = (uint64_t)(uintptr_t)p;
    if (v < 0x100000000ull)         return (int)(int64_t)v;
    if (v >= 0xFFFFFFFF00000000ull) return (int)(int64_t)v;

    cudaPointerAttributes a;
    cudaError_t e = cudaPointerGetAttributes(&a, p);
    if (e == cudaSuccess) {
        if (a.type == cudaMemoryTypeHost || a.type == cudaMemoryTypeUnregistered)
            return *(const int*)p;
        if (a.type == cudaMemoryTypeManaged && a.hostPointer)
            return *(const int*)a.hostPointer;
        if (a.type == cudaMemoryTypeDevice) { *mode = 1; *dev_ptr = (const int*)p; return 0; }
    }
    cudaGetLastError();
    return *(const int*)p;
}

extern "C" void kernel_launch(void* const* d_in, const int* in_sizes, int n_in,
                              void* d_out, int out_size)
{
    // 0=explicit_mask, 1=q_segment_ids, 2=kv_segment_ids,
    // 3=q_len, 4=k_len, 5=causal_offset, 6=window
    const int* expl = (const int*)d_in[0];
    const int* qseg = (const int*)d_in[1];
    const int* kseg = (const int*)d_in[2];
    float*     out  = (float*)d_out;

    const long long s_expl = in_sizes[0];                // qlen*klen
    const int B    = (int)((long long)out_size / s_expl);
    const int qlen = in_sizes[1] / B;
    const int klen = in_sizes[2] / B;

    int m5, m6;
    const int *p5, *p6;
    const int off = read_scalar(d_in[5], &m5, &p5);
    const int win = read_scalar(d_in[6], &m6, &p6);
    const int* off_dev = (m5 == 1) ? p5 : nullptr;
    const int* win_dev = (m6 == 1) ? p6 : nullptr;

    if ((klen & 3) == 0) {
        const int nrows = B * qlen;
        int nsm = 148;
        cudaDeviceGetAttribute(&nsm, cudaDevAttrMultiProcessorCount, 0);
        int grid = nsm * 4;                    // 4 x 512-thread blocks per SM
        if (grid > nrows) grid = nrows;
        mask_row_kernel<<<grid, 512>>>(expl, qseg, kseg, out,
                                       qlen, klen, B, nrows, off, win,
                                       off_dev, win_dev);
    } else {
        const long long total = out_size;
        const int threads = 256;
        const long long blocks = (total + threads - 1) / threads;
        mask1_kernel<<<(unsigned)blocks, threads>>>(expl, qseg, kseg, out,
                                                    qlen, klen, off, win,
                                                    off_dev, win_dev, total);
    }
}

// round 11
// speedup vs baseline: 1.2846x; 1.2846x over previous
#include <cuda_runtime.h>
#include <stdint.h>

// out[b,q,k] (f32 0/1) = (kmin <= k <= kmax) & (expl[q,k]!=0) & (qseg[b,q]==kseg[b,k])
//   kmax = q + min(off,0), kmin = q - win + 1
//
// One block per output row (b,q), batch-inner so the B batches of a q-row are
// adjacent in launch order -> explicit row read from DRAM once, reused via L2.
// Band chunk range [lo,hi) precomputed per row; outside it, pure branchless
// zero-store streams (plain STG.128 — .cs measured harmful in R9).

__global__ void __launch_bounds__(256)
mask_row_kernel(const int* __restrict__ expl,   // [qlen, klen]
                const int* __restrict__ qseg,   // [B, qlen]
                const int* __restrict__ kseg,   // [B, klen]
                float*     __restrict__ out,    // [B, qlen, klen]
                int qlen, int klen, int B,
                int off_imm, int win_imm,
                const int* off_dev, const int* win_dev)
{
    const int rowid = blockIdx.x;          // = q * B + b  (batch-inner)
    const int b = rowid % B;
    const int q = rowid / B;

    const int off = off_dev ? __ldg(off_dev) : off_imm;
    const int win = win_dev ? __ldg(win_dev) : win_imm;

    const int kmax = q + (off < 0 ? off : 0);
    const int kmin = q - win + 1;

    float4*     orow = reinterpret_cast<float4*>(out + ((long long)b * qlen + q) * klen);
    const int4* erow = reinterpret_cast<const int4*>(expl + (long long)q * klen);
    const int4* krow = reinterpret_cast<const int4*>(kseg + (long long)b * klen);

    const int n4 = klen >> 2;
    int lo = kmin >> 2;           if (lo < 0)  lo = 0;   if (lo > n4) lo = n4;
    int hi = (kmax >> 2) + 1;     if (hi > n4) hi = n4;  if (hi < lo) hi = lo;

    const int tid = threadIdx.x;
    const int bs  = blockDim.x;
    const float4 zero = make_float4(0.f, 0.f, 0.f, 0.f);

    // leading zeros: branchless streaming stores, 8 independent STG.128/thread/pass
    #pragma unroll 8
    for (int i = tid; i < lo; i += bs)
        orow[i] = zero;

    // band: compute
    if (tid < hi - lo) {
        const int qs = __ldg(qseg + b * qlen + q);
        for (int i = lo + tid; i < hi; i += bs) {
            const int k0 = i << 2;
            const int4 e  = __ldg(erow + i);
            const int4 ks = __ldg(krow + i);
            float4 r;
            r.x = ((k0   >= kmin) & (k0   <= kmax) & (e.x != 0) & (qs == ks.x)) ? 1.f : 0.f;
            r.y = ((k0+1 >= kmin) & (k0+1 <= kmax) & (e.y != 0) & (qs == ks.y)) ? 1.f : 0.f;
            r.z = ((k0+2 >= kmin) & (k0+2 <= kmax) & (e.z != 0) & (qs == ks.z)) ? 1.f : 0.f;
            r.w = ((k0+3 >= kmin) & (k0+3 <= kmax) & (e.w != 0) & (qs == ks.w)) ? 1.f : 0.f;
            orow[i] = r;
        }
    }

    // trailing zeros
    #pragma unroll 8
    for (int i = hi + tid; i < n4; i += bs)
        orow[i] = zero;
}

// Elementwise fallback (klen % 4 != 0; not expected for 8192).
__global__ void __launch_bounds__(256)
mask1_kernel(const int* __restrict__ expl,
             const int* __restrict__ qseg,
             const int* __restrict__ kseg,
             float*     __restrict__ out,
             int qlen, int klen, int off, int win,
             const int* off_dev, const int* win_dev,
             long long total)
{
    long long idx = (long long)blockIdx.x * blockDim.x + threadIdx.x;
    if (idx >= total) return;
    if (off_dev) off = __ldg(off_dev);
    if (win_dev) win = __ldg(win_dev);
    const int k = (int)(idx % klen);
    const long long row = idx / klen;
    const int q = (int)(row % qlen);
    const int b = (int)(row / qlen);
    const int d = q - k;
    const bool ok = (d >= -off) & (d >= 0) & (d < win)
                  & (expl[(long long)q * klen + k] != 0)
                  & (qseg[row] == kseg[(long long)b * klen + k]);
    out[idx] = ok ? 1.f : 0.f;
}

// Decode a size-1 scalar input. mode: 0 = immediate value, 1 = device pointer.
static int read_scalar(const void* p, int* mode, const int** dev_ptr)
{
    *mode = 0; *dev_ptr = nullptr;
    const uint64_t v = (uint64_t)(uintptr_t)p;
    if (v < 0x100000000ull)         return (int)(int64_t)v;
    if (v >= 0xFFFFFFFF00000000ull) return (int)(int64_t)v;

    cudaPointerAttributes a;
    cudaError_t e = cudaPointerGetAttributes(&a, p);
    if (e == cudaSuccess) {
        if (a.type == cudaMemoryTypeHost || a.type == cudaMemoryTypeUnregistered)
            return *(const int*)p;
        if (a.type == cudaMemoryTypeManaged && a.hostPointer)
            return *(const int*)a.hostPointer;
        if (a.type == cudaMemoryTypeDevice) { *mode = 1; *dev_ptr = (const int*)p; return 0; }
    }
    cudaGetLastError();
    return *(const int*)p;
}

extern "C" void kernel_launch(void* const* d_in, const int* in_sizes, int n_in,
                              void* d_out, int out_size)
{
    // 0=explicit_mask, 1=q_segment_ids, 2=kv_segment_ids,
    // 3=q_len, 4=k_len, 5=causal_offset, 6=window
    const int* expl = (const int*)d_in[0];
    const int* qseg = (const int*)d_in[1];
    const int* kseg = (const int*)d_in[2];
    float*     out  = (float*)d_out;

    const long long s_expl = in_sizes[0];                // qlen*klen
    const int B    = (int)((long long)out_size / s_expl);
    const int qlen = in_sizes[1] / B;
    const int klen = in_sizes[2] / B;

    int m5, m6;
    const int *p5, *p6;
    const int off = read_scalar(d_in[5], &m5, &p5);
    const int win = read_scalar(d_in[6], &m6, &p6);
    const int* off_dev = (m5 == 1) ? p5 : nullptr;
    const int* win_dev = (m6 == 1) ? p6 : nullptr;

    if ((klen & 3) == 0) {
        const int nrows = B * qlen;
        mask_row_kernel<<<nrows, 256>>>(expl, qseg, kseg, out,
                                        qlen, klen, B, off, win,
                                        off_dev, win_dev);
    } else {
        const long long total = out_size;
        const int threads = 256;
        const long long blocks = (total + threads - 1) / threads;
        mask1_kernel<<<(unsigned)blocks, threads>>>(expl, qseg, kseg, out,
                                                    qlen, klen, off, win,
                                                    off_dev, win_dev, total);
    }
}